// round 9
// baseline (speedup 1.0000x reference)
#include <cuda_runtime.h>
#include <math.h>

#define Bn     2
#define NBOX   32
#define NTH    4
#define ROIW   28
#define Hh     768
#define Ww     704
#define HWp    (Hh*Ww)          // 540672
#define NSTUFF 6
#define NCLS   10
#define Lout   39               // 1 + NSTUFF + NBOX
#define TLX    64               // tile width (px)
#define TLY    8                // tile height (px)

struct BoxMeta {
    int   iy0, ix0, iy1, ix1;     // in2 rect (half-open)
    int   py0, px0, py1, px1;     // paste/inside rect (half-open)
    float fy0, fx0;               // floor(bbx0), floor(bbx1)
    float sysc, sxsc;             // 28/h, 28/w
    int   semc;                   // 6 + cls
    int   mskoff;                 // float offset of selected 28x28 mask
};

__device__ int           g_counts[Bn][NBOX*NCLS];   // zero-init; passB resets after read
__device__ int           g_sflag[Bn][NSTUFF];       // zero-init; passB resets after read
__device__ float         g_lut[Bn][NSTUFF+NBOX];
__device__ unsigned char g_pp[Bn*HWp];

__device__ __forceinline__ float sigm(float x) {
    if (x >= 0.0f) return 1.0f / (1.0f + expf(-x));
    float e = expf(x);
    return e / (1.0f + e);
}

// ---------------- pass A: per-pixel argmaxes + histograms (tile-culled) ----------------
__global__ void __launch_bounds__(128) k_passA(const float* __restrict__ sem,
                                               const float* __restrict__ roi,
                                               const float* __restrict__ bbx,
                                               const int*   __restrict__ cls) {
    __shared__ BoxMeta  sb[NBOX];
    __shared__ int      scnt[NBOX*NCLS];
    __shared__ int      sfl[NSTUFF];
    __shared__ unsigned s_tm;

    const int b   = blockIdx.z;
    const int t   = threadIdx.x;
    const int tx0 = blockIdx.x * TLX;
    const int ty0 = blockIdx.y * TLY;

    // warp 0: compute box meta + tile-intersection ballot
    if (t < NBOX) {
        int gi = b*NBOX + t;
        float b0 = bbx[gi*4+0], b1 = bbx[gi*4+1], b2 = bbx[gi*4+2], b3 = bbx[gi*4+3];
        int y0f = (int)floorf(b0), x0f = (int)floorf(b1);
        int y1f = (int)floorf(b2), x1f = (int)floorf(b3);
        BoxMeta m;
        m.iy0 = y0f;  m.ix0 = x0f;
        m.iy1 = (int)(rintf(b2) + 1.0f);
        m.ix1 = (int)(rintf(b3) + 1.0f);
        m.py0 = max(y0f, 0);      m.px0 = max(x0f, 0);
        m.py1 = min(y1f + 1, Hh); m.px1 = min(x1f + 1, Ww);
        float hh = (float)max(y1f - y0f + 1, 1);
        float ww = (float)max(x1f - x0f + 1, 1);
        m.sysc = 28.0f / hh; m.sxsc = 28.0f / ww;
        m.fy0 = (float)y0f;  m.fx0 = (float)x0f;
        int c = cls[gi];
        c = max(0, min(c, NTH-1));
        m.semc = NSTUFF + c;
        m.mskoff = (gi * NTH + c) * (ROIW * ROIW);
        sb[t] = m;
        bool ov = (m.iy0 < ty0+TLY) && (m.iy1 > ty0) && (m.ix0 < tx0+TLX) && (m.ix1 > tx0);
        unsigned msk = __ballot_sync(0xffffffffu, ov);
        if (t == 0) s_tm = msk;
    }
    for (int i = t; i < NBOX*NCLS; i += 128) scnt[i] = 0;
    if (t < NSTUFF) sfl[t] = 0;
    __syncthreads();
    const unsigned tm = s_tm;

    const int x0  = tx0 + (t & 15) * 4;
    const int y   = ty0 + (t >> 4);
    const int pix = y * Ww + x0;
    const float4* s4 = (const float4*)sem + (size_t)b * NCLS * (HWp/4) + (pix >> 2);

    // 10-channel argmaxes for 4 pixels; cache thing channels 6..9
    float4 v = s4[0];
    float best[4] = {v.x, v.y, v.z, v.w};
    float smax[4] = {v.x, v.y, v.z, v.w};
    int   bi[4]   = {0,0,0,0};
    int   sp[4]   = {0,0,0,0};
    float th0[4], th1[4], th2[4], th3[4];
    #pragma unroll
    for (int c = 1; c < NCLS; ++c) {
        float4 u4 = s4[(size_t)c * (HWp/4)];
        float uu[4] = {u4.x, u4.y, u4.z, u4.w};
        #pragma unroll
        for (int p = 0; p < 4; ++p) {
            if (uu[p] > smax[p]) { smax[p] = uu[p]; sp[p] = c; }
            if (c < NSTUFF) {
                if (uu[p] > best[p]) { best[p] = uu[p]; bi[p] = c; }
            } else {
                if (c == 6) th0[p] = uu[p];
                if (c == 7) th1[p] = uu[p];
                if (c == 8) th2[p] = uu[p];
                if (c == 9) th3[p] = uu[p];
            }
        }
    }

    const float CNEG = (2.0f * sigm(-100.0f)) * (-200.0f);
    unsigned char outp[4];

    #pragma unroll
    for (int p = 0; p < 4; ++p) {
        const int x = x0 + p;
        // per-pixel cover bitmap over tile-culled boxes
        unsigned cov = 0, mm = tm;
        while (mm) {
            int n = __ffs(mm) - 1; mm &= mm - 1;
            const BoxMeta& m = sb[n];
            if (y >= m.iy0 && y < m.iy1 && x >= m.ix0 && x < m.ix1) cov |= (1u << n);
        }
        unsigned notc = ~cov;
        int ncneg = notc ? (__ffs(notc) - 1) : 32;   // first NON-covered box index
        bool applied = false;
        float bst = best[p]; int bb = bi[p];
        mm = cov;
        while (mm) {
            int n = __ffs(mm) - 1; mm &= mm - 1;
            if (!applied && ncneg < n) {               // CNEG candidate sits before box n
                if (CNEG > bst) { bst = CNEG; bb = NSTUFF + ncneg; }
                applied = true;
            }
            const BoxMeta& m = sb[n];
            int ci = m.semc - NSTUFF;
            float pi = (ci == 0) ? th0[p] : (ci == 1) ? th1[p] : (ci == 2) ? th2[p] : th3[p];
            float pm;
            if (y >= m.py0 && y < m.py1 && x >= m.px0 && x < m.px1) {
                float sy = ((float)y - m.fy0 + 0.5f) * m.sysc - 0.5f;
                sy = fminf(fmaxf(sy, 0.0f), 27.0f);
                float sx = ((float)x - m.fx0 + 0.5f) * m.sxsc - 0.5f;
                sx = fminf(fmaxf(sx, 0.0f), 27.0f);
                int yl = (int)sy, xl = (int)sx;
                int yh = min(yl + 1, 27), xh = min(xl + 1, 27);
                float wy = sy - (float)yl, wx = sx - (float)xl;
                const float* mk = roi + m.mskoff;
                float a  = mk[yl*ROIW + xl], bq = mk[yl*ROIW + xh];
                float cq = mk[yh*ROIW + xl], dq = mk[yh*ROIW + xh];
                float r0 = a  * (1.0f - wy) + cq * wy;
                float r1 = bq * (1.0f - wy) + dq * wy;
                pm = r0 * (1.0f - wx) + r1 * wx;
            } else {
                pm = -100.0f;
            }
            float val = (sigm(pi) + sigm(pm)) * (pi + pm);
            if (val > bst) { bst = val; bb = NSTUFF + n; }
        }
        if (!applied && ncneg < 32) {
            if (CNEG > bst) { bst = CNEG; bb = NSTUFF + ncneg; }
        }
        outp[p] = (unsigned char)bb;
        if (bb >= NSTUFF) atomicAdd(&scnt[(bb - NSTUFF)*NCLS + sp[p]], 1);
        else              sfl[bb] = 1;
    }

    *(uchar4*)(g_pp + (size_t)b*HWp + pix) = make_uchar4(outp[0], outp[1], outp[2], outp[3]);
    __syncthreads();

    for (int i = t; i < NBOX*NCLS; i += 128) {
        int vv = scnt[i];
        if (vv) atomicAdd(&g_counts[b][i], vv);
    }
    if (t < NSTUFF && sfl[t]) g_sflag[b][t] = 1;
}

// ---------------- pass B: label logic + counter reset (for next graph replay) ----------------
__global__ void k_passB(const int* __restrict__ cls, float* __restrict__ out) {
    int t = threadIdx.x;
    if (t < Bn) {
        int b = t;
        int  idxv[NBOX], semval[NBOX];
        bool present[NBOX], tostuff[NBOX];
        int run = 0;
        for (int n = 0; n < NBOX; ++n) {
            int s = 0, mmx = 0, mj = 0;
            for (int c = 0; c < NCLS; ++c) {
                int v = g_counts[b][n*NCLS + c];
                s += v;
                if (v > mmx) { mmx = v; mj = c; }
            }
            bool pr = s > 0;
            present[n] = pr;
            if (pr) run++;
            idxv[n] = run - 1;
            int thing = cls[b*NBOX + n] + NSTUFF;
            bool ts = (mj != thing) && (2*mmx >= max(s, 1)) && (mj < NSTUFF);
            tostuff[n] = ts;
            semval[n]  = ts ? mj : thing;
        }

        bool sp_[NSTUFF];
        for (int s = 0; s < NSTUFF; ++s) sp_[s] = (g_sflag[b][s] != 0);
        for (int n = 0; n < NBOX; ++n)
            if (present[n] && tostuff[n]) sp_[semval[n]] = true;

        int s_rank[NSTUFF]; int r = 0;
        for (int s = 0; s < NSTUFF; ++s) { if (sp_[s]) r++; s_rank[s] = r - 1; }
        int nstuff = r;

        bool ip[NBOX];
        for (int i = 0; i < NBOX; ++i) ip[i] = false;
        for (int n = 0; n < NBOX; ++n)
            if (present[n] && !tostuff[n]) ip[idxv[n]] = true;
        int i_rank[NBOX]; int r2 = 0;
        for (int i = 0; i < NBOX; ++i) { if (ip[i]) r2++; i_rank[i] = r2 - 1; }

        for (int c = 0; c < NSTUFF; ++c) g_lut[b][c] = (float)(1 + s_rank[c]);
        for (int n = 0; n < NBOX; ++n) {
            int v = 0;
            if (present[n])
                v = tostuff[n] ? (1 + s_rank[semval[n]])
                               : (1 + nstuff + i_rank[idxv[n]]);
            g_lut[b][NSTUFF + n] = (float)v;
        }

        int co[Lout];
        for (int i = 0; i < Lout; ++i) co[i] = 255;
        for (int s = 0; s < NSTUFF; ++s)
            if (sp_[s]) co[1 + s_rank[s]] = s;
        for (int n = 0; n < NBOX; ++n)
            if (present[n] && !tostuff[n]) co[1 + nstuff + i_rank[idxv[n]]] = semval[n];

        float* cbase = out + Bn*HWp + b*Lout;
        for (int i = 0; i < Lout; ++i) cbase[i] = (float)co[i];
        float* ibase = out + Bn*HWp + Bn*Lout + b*Lout;
        for (int i = 0; i < Lout; ++i) ibase[i] = 0.0f;
    }
    __syncthreads();
    // reset accumulators so the next graph replay starts from zero (deterministic)
    for (int i = t; i < Bn*NBOX*NCLS; i += blockDim.x) ((int*)g_counts)[i] = 0;
    if (t < Bn*NSTUFF) ((int*)g_sflag)[t] = 0;
}

// ---------------- pass C: seam remap (2 independent quads/thread, one per batch) ----------------
__global__ void __launch_bounds__(256) k_passC(float* __restrict__ out) {
    const int half = HWp / 4;                 // quads per batch
    int i = blockIdx.x * 256 + threadIdx.x;   // 0 .. half-1
    uchar4 p0 = ((const uchar4*)g_pp)[i];
    uchar4 p1 = ((const uchar4*)g_pp)[i + half];
    const float* l0 = g_lut[0];
    const float* l1 = g_lut[1];
    float4 o0, o1;
    o0.x = __ldg(&l0[p0.x]); o0.y = __ldg(&l0[p0.y]);
    o0.z = __ldg(&l0[p0.z]); o0.w = __ldg(&l0[p0.w]);
    o1.x = __ldg(&l1[p1.x]); o1.y = __ldg(&l1[p1.y]);
    o1.z = __ldg(&l1[p1.z]); o1.w = __ldg(&l1[p1.w]);
    ((float4*)out)[i]        = o0;
    ((float4*)out)[i + half] = o1;
}

extern "C" void kernel_launch(void* const* d_in, const int* in_sizes, int n_in,
                              void* d_out, int out_size) {
    const float* sem = nullptr;   // 10813440
    const float* roi = nullptr;   // 200704
    const float* bbx = nullptr;   // 256
    const int*   cls = nullptr;   // 64
    for (int i = 0; i < n_in; ++i) {
        switch (in_sizes[i]) {
            case 10813440: sem = (const float*)d_in[i]; break;
            case 200704:   roi = (const float*)d_in[i]; break;
            case 256:      bbx = (const float*)d_in[i]; break;
            case 64:       cls = (const int*)d_in[i];   break;
            default: break;
        }
    }
    float* out = (float*)d_out;

    k_passA<<<dim3(Ww/TLX, Hh/TLY, Bn), 128>>>(sem, roi, bbx, cls);
    k_passB<<<1, 64>>>(cls, out);
    k_passC<<<(HWp/4)/256, 256>>>(out);
}

// round 10
// speedup vs baseline: 1.0452x; 1.0452x over previous
#include <cuda_runtime.h>
#include <math.h>

#define Bn     2
#define NBOX   32
#define NTH    4
#define ROIW   28
#define Hh     768
#define Ww     704
#define HWp    (Hh*Ww)          // 540672
#define NSTUFF 6
#define NCLS   10
#define Lout   39               // 1 + NSTUFF + NBOX
#define TLX    64               // tile width (px)
#define TLY    8                // tile height (px)

struct BoxMeta {
    int   iy0, ix0, iy1, ix1;     // in2 rect (half-open)
    int   py0, px0, py1, px1;     // paste/inside rect (half-open)
    float fy0, fx0;               // floor(bbx0), floor(bbx1)
    float sysc, sxsc;             // 28/h, 28/w
    int   semc;                   // 6 + cls
    int   mskoff;                 // float offset of selected 28x28 mask
};

__device__ int           g_counts[Bn][NBOX*NCLS];   // zero-init; passB resets after read
__device__ int           g_sflag[Bn][NSTUFF];       // zero-init; passB resets after read
__device__ float         g_lut[Bn][NSTUFF+NBOX];
__device__ unsigned char g_pp[Bn*HWp];

__device__ __forceinline__ float sigm(float x) {
    if (x >= 0.0f) return 1.0f / (1.0f + expf(-x));
    float e = expf(x);
    return e / (1.0f + e);
}

// ---------------- pass A: per-pixel argmaxes + histograms (tile-culled) ----------------
__global__ void __launch_bounds__(128) k_passA(const float* __restrict__ sem,
                                               const float* __restrict__ roi,
                                               const float* __restrict__ bbx,
                                               const int*   __restrict__ cls) {
    __shared__ BoxMeta  sb[NBOX];
    __shared__ int      scnt[NBOX*NCLS];
    __shared__ int      sfl[NSTUFF];
    __shared__ unsigned s_tm;

    const int b   = blockIdx.z;
    const int t   = threadIdx.x;
    const int tx0 = blockIdx.x * TLX;
    const int ty0 = blockIdx.y * TLY;

    // warp 0: compute box meta + tile-intersection ballot
    if (t < NBOX) {
        int gi = b*NBOX + t;
        float b0 = bbx[gi*4+0], b1 = bbx[gi*4+1], b2 = bbx[gi*4+2], b3 = bbx[gi*4+3];
        int y0f = (int)floorf(b0), x0f = (int)floorf(b1);
        int y1f = (int)floorf(b2), x1f = (int)floorf(b3);
        BoxMeta m;
        m.iy0 = y0f;  m.ix0 = x0f;
        m.iy1 = (int)(rintf(b2) + 1.0f);
        m.ix1 = (int)(rintf(b3) + 1.0f);
        m.py0 = max(y0f, 0);      m.px0 = max(x0f, 0);
        m.py1 = min(y1f + 1, Hh); m.px1 = min(x1f + 1, Ww);
        float hh = (float)max(y1f - y0f + 1, 1);
        float ww = (float)max(x1f - x0f + 1, 1);
        m.sysc = 28.0f / hh; m.sxsc = 28.0f / ww;
        m.fy0 = (float)y0f;  m.fx0 = (float)x0f;
        int c = cls[gi];
        c = max(0, min(c, NTH-1));
        m.semc = NSTUFF + c;
        m.mskoff = (gi * NTH + c) * (ROIW * ROIW);
        sb[t] = m;
        bool ov = (m.iy0 < ty0+TLY) && (m.iy1 > ty0) && (m.ix0 < tx0+TLX) && (m.ix1 > tx0);
        unsigned msk = __ballot_sync(0xffffffffu, ov);
        if (t == 0) s_tm = msk;
    }
    for (int i = t; i < NBOX*NCLS; i += 128) scnt[i] = 0;
    if (t < NSTUFF) sfl[t] = 0;
    __syncthreads();
    const unsigned tm = s_tm;

    const int x0  = tx0 + (t & 15) * 4;
    const int y   = ty0 + (t >> 4);
    const int pix = y * Ww + x0;
    const float4* s4 = (const float4*)sem + (size_t)b * NCLS * (HWp/4) + (pix >> 2);

    // 10-channel argmaxes for 4 pixels; cache thing channels 6..9
    float4 v = s4[0];
    float best[4] = {v.x, v.y, v.z, v.w};
    float smax[4] = {v.x, v.y, v.z, v.w};
    int   bi[4]   = {0,0,0,0};
    int   sp[4]   = {0,0,0,0};
    float th0[4], th1[4], th2[4], th3[4];
    #pragma unroll
    for (int c = 1; c < NCLS; ++c) {
        float4 u4 = s4[(size_t)c * (HWp/4)];
        float uu[4] = {u4.x, u4.y, u4.z, u4.w};
        #pragma unroll
        for (int p = 0; p < 4; ++p) {
            if (uu[p] > smax[p]) { smax[p] = uu[p]; sp[p] = c; }
            if (c < NSTUFF) {
                if (uu[p] > best[p]) { best[p] = uu[p]; bi[p] = c; }
            } else {
                if (c == 6) th0[p] = uu[p];
                if (c == 7) th1[p] = uu[p];
                if (c == 8) th2[p] = uu[p];
                if (c == 9) th3[p] = uu[p];
            }
        }
    }

    const float CNEG = (2.0f * sigm(-100.0f)) * (-200.0f);
    unsigned char outp[4];

    #pragma unroll
    for (int p = 0; p < 4; ++p) {
        const int x = x0 + p;
        // per-pixel cover bitmap over tile-culled boxes
        unsigned cov = 0, mm = tm;
        while (mm) {
            int n = __ffs(mm) - 1; mm &= mm - 1;
            const BoxMeta& m = sb[n];
            if (y >= m.iy0 && y < m.iy1 && x >= m.ix0 && x < m.ix1) cov |= (1u << n);
        }
        unsigned notc = ~cov;
        int ncneg = notc ? (__ffs(notc) - 1) : 32;   // first NON-covered box index
        bool applied = false;
        float bst = best[p]; int bb = bi[p];
        mm = cov;
        while (mm) {
            int n = __ffs(mm) - 1; mm &= mm - 1;
            if (!applied && ncneg < n) {               // CNEG candidate sits before box n
                if (CNEG > bst) { bst = CNEG; bb = NSTUFF + ncneg; }
                applied = true;
            }
            const BoxMeta& m = sb[n];
            int ci = m.semc - NSTUFF;
            float pi = (ci == 0) ? th0[p] : (ci == 1) ? th1[p] : (ci == 2) ? th2[p] : th3[p];
            float pm;
            if (y >= m.py0 && y < m.py1 && x >= m.px0 && x < m.px1) {
                float sy = ((float)y - m.fy0 + 0.5f) * m.sysc - 0.5f;
                sy = fminf(fmaxf(sy, 0.0f), 27.0f);
                float sx = ((float)x - m.fx0 + 0.5f) * m.sxsc - 0.5f;
                sx = fminf(fmaxf(sx, 0.0f), 27.0f);
                int yl = (int)sy, xl = (int)sx;
                int yh = min(yl + 1, 27), xh = min(xl + 1, 27);
                float wy = sy - (float)yl, wx = sx - (float)xl;
                const float* mk = roi + m.mskoff;
                float a  = mk[yl*ROIW + xl], bq = mk[yl*ROIW + xh];
                float cq = mk[yh*ROIW + xl], dq = mk[yh*ROIW + xh];
                float r0 = a  * (1.0f - wy) + cq * wy;
                float r1 = bq * (1.0f - wy) + dq * wy;
                pm = r0 * (1.0f - wx) + r1 * wx;
            } else {
                pm = -100.0f;
            }
            float val = (sigm(pi) + sigm(pm)) * (pi + pm);
            if (val > bst) { bst = val; bb = NSTUFF + n; }
        }
        if (!applied && ncneg < 32) {
            if (CNEG > bst) { bst = CNEG; bb = NSTUFF + ncneg; }
        }
        outp[p] = (unsigned char)bb;
        if (bb >= NSTUFF) atomicAdd(&scnt[(bb - NSTUFF)*NCLS + sp[p]], 1);
        else              sfl[bb] = 1;
    }

    *(uchar4*)(g_pp + (size_t)b*HWp + pix) = make_uchar4(outp[0], outp[1], outp[2], outp[3]);
    __syncthreads();

    for (int i = t; i < NBOX*NCLS; i += 128) {
        int vv = scnt[i];
        if (vv) atomicAdd(&g_counts[b][i], vv);
    }
    if (t < NSTUFF && sfl[t]) g_sflag[b][t] = 1;
}

// ---------------- pass B: label logic + counter reset (for next graph replay) ----------------
__global__ void k_passB(const int* __restrict__ cls, float* __restrict__ out) {
    int t = threadIdx.x;
    if (t < Bn) {
        int b = t;
        int  idxv[NBOX], semval[NBOX];
        bool present[NBOX], tostuff[NBOX];
        int run = 0;
        for (int n = 0; n < NBOX; ++n) {
            int s = 0, mmx = 0, mj = 0;
            for (int c = 0; c < NCLS; ++c) {
                int v = g_counts[b][n*NCLS + c];
                s += v;
                if (v > mmx) { mmx = v; mj = c; }
            }
            bool pr = s > 0;
            present[n] = pr;
            if (pr) run++;
            idxv[n] = run - 1;
            int thing = cls[b*NBOX + n] + NSTUFF;
            bool ts = (mj != thing) && (2*mmx >= max(s, 1)) && (mj < NSTUFF);
            tostuff[n] = ts;
            semval[n]  = ts ? mj : thing;
        }

        bool sp_[NSTUFF];
        for (int s = 0; s < NSTUFF; ++s) sp_[s] = (g_sflag[b][s] != 0);
        for (int n = 0; n < NBOX; ++n)
            if (present[n] && tostuff[n]) sp_[semval[n]] = true;

        int s_rank[NSTUFF]; int r = 0;
        for (int s = 0; s < NSTUFF; ++s) { if (sp_[s]) r++; s_rank[s] = r - 1; }
        int nstuff = r;

        bool ip[NBOX];
        for (int i = 0; i < NBOX; ++i) ip[i] = false;
        for (int n = 0; n < NBOX; ++n)
            if (present[n] && !tostuff[n]) ip[idxv[n]] = true;
        int i_rank[NBOX]; int r2 = 0;
        for (int i = 0; i < NBOX; ++i) { if (ip[i]) r2++; i_rank[i] = r2 - 1; }

        for (int c = 0; c < NSTUFF; ++c) g_lut[b][c] = (float)(1 + s_rank[c]);
        for (int n = 0; n < NBOX; ++n) {
            int v = 0;
            if (present[n])
                v = tostuff[n] ? (1 + s_rank[semval[n]])
                               : (1 + nstuff + i_rank[idxv[n]]);
            g_lut[b][NSTUFF + n] = (float)v;
        }

        int co[Lout];
        for (int i = 0; i < Lout; ++i) co[i] = 255;
        for (int s = 0; s < NSTUFF; ++s)
            if (sp_[s]) co[1 + s_rank[s]] = s;
        for (int n = 0; n < NBOX; ++n)
            if (present[n] && !tostuff[n]) co[1 + nstuff + i_rank[idxv[n]]] = semval[n];

        float* cbase = out + Bn*HWp + b*Lout;
        for (int i = 0; i < Lout; ++i) cbase[i] = (float)co[i];
        float* ibase = out + Bn*HWp + Bn*Lout + b*Lout;
        for (int i = 0; i < Lout; ++i) ibase[i] = 0.0f;
    }
    __syncthreads();
    // reset accumulators so the next graph replay starts from zero (deterministic)
    for (int i = t; i < Bn*NBOX*NCLS; i += blockDim.x) ((int*)g_counts)[i] = 0;
    if (t < Bn*NSTUFF) ((int*)g_sflag)[t] = 0;
}

// ---------------- pass C: seam remap (2 independent quads/thread, one per batch) ----------------
__global__ void __launch_bounds__(256) k_passC(float* __restrict__ out) {
    const int half = HWp / 4;                 // quads per batch
    int i = blockIdx.x * 256 + threadIdx.x;   // 0 .. half-1
    uchar4 p0 = ((const uchar4*)g_pp)[i];
    uchar4 p1 = ((const uchar4*)g_pp)[i + half];
    const float* l0 = g_lut[0];
    const float* l1 = g_lut[1];
    float4 o0, o1;
    o0.x = __ldg(&l0[p0.x]); o0.y = __ldg(&l0[p0.y]);
    o0.z = __ldg(&l0[p0.z]); o0.w = __ldg(&l0[p0.w]);
    o1.x = __ldg(&l1[p1.x]); o1.y = __ldg(&l1[p1.y]);
    o1.z = __ldg(&l1[p1.z]); o1.w = __ldg(&l1[p1.w]);
    ((float4*)out)[i]        = o0;
    ((float4*)out)[i + half] = o1;
}

extern "C" void kernel_launch(void* const* d_in, const int* in_sizes, int n_in,
                              void* d_out, int out_size) {
    const float* sem = nullptr;   // 10813440
    const float* roi = nullptr;   // 200704
    const float* bbx = nullptr;   // 256
    const int*   cls = nullptr;   // 64
    for (int i = 0; i < n_in; ++i) {
        switch (in_sizes[i]) {
            case 10813440: sem = (const float*)d_in[i]; break;
            case 200704:   roi = (const float*)d_in[i]; break;
            case 256:      bbx = (const float*)d_in[i]; break;
            case 64:       cls = (const int*)d_in[i];   break;
            default: break;
        }
    }
    float* out = (float*)d_out;

    k_passA<<<dim3(Ww/TLX, Hh/TLY, Bn), 128>>>(sem, roi, bbx, cls);
    k_passB<<<1, 64>>>(cls, out);
    k_passC<<<(HWp/4)/256, 256>>>(out);
}

// round 11
// speedup vs baseline: 1.0741x; 1.0277x over previous
#include <cuda_runtime.h>
#include <math.h>

#define Bn     2
#define NBOX   32
#define NTH    4
#define ROIW   28
#define Hh     768
#define Ww     704
#define HWp    (Hh*Ww)          // 540672
#define NSTUFF 6
#define NCLS   10
#define Lout   39               // 1 + NSTUFF + NBOX
#define TLX    64               // tile width (px)
#define TLY    8                // tile height (px)

struct BoxMeta {
    int   iy0, ix0, iy1, ix1;     // in2 rect (half-open)
    int   py0, px0, py1, px1;     // paste/inside rect (half-open)
    float fy0, fx0;               // floor(bbx0), floor(bbx1)
    float sysc, sxsc;             // 28/h, 28/w
    int   semc;                   // 6 + cls
    int   mskoff;                 // float offset of selected 28x28 mask
};

__device__ int           g_counts[Bn][NBOX*NCLS];   // zero-init; passB resets after read
__device__ int           g_sflag[Bn][NSTUFF];       // zero-init; passB resets after read
__device__ float         g_lut[Bn][NSTUFF+NBOX];
__device__ unsigned char g_pp[Bn*HWp];

__device__ __forceinline__ float sigm(float x) {
    if (x >= 0.0f) return 1.0f / (1.0f + expf(-x));
    float e = expf(x);
    return e / (1.0f + e);
}

// ---------------- pass A: per-pixel argmaxes + histograms (tile-culled) ----------------
__global__ void __launch_bounds__(128) k_passA(const float* __restrict__ sem,
                                               const float* __restrict__ roi,
                                               const float* __restrict__ bbx,
                                               const int*   __restrict__ cls) {
    __shared__ BoxMeta  sb[NBOX];
    __shared__ int      scnt[NBOX*NCLS];
    __shared__ int      sfl[NSTUFF];
    __shared__ unsigned s_tm;

    const int b   = blockIdx.z;
    const int t   = threadIdx.x;
    const int tx0 = blockIdx.x * TLX;
    const int ty0 = blockIdx.y * TLY;

    // warp 0: compute box meta + tile-intersection ballot
    if (t < NBOX) {
        int gi = b*NBOX + t;
        float b0 = bbx[gi*4+0], b1 = bbx[gi*4+1], b2 = bbx[gi*4+2], b3 = bbx[gi*4+3];
        int y0f = (int)floorf(b0), x0f = (int)floorf(b1);
        int y1f = (int)floorf(b2), x1f = (int)floorf(b3);
        BoxMeta m;
        m.iy0 = y0f;  m.ix0 = x0f;
        m.iy1 = (int)(rintf(b2) + 1.0f);
        m.ix1 = (int)(rintf(b3) + 1.0f);
        m.py0 = max(y0f, 0);      m.px0 = max(x0f, 0);
        m.py1 = min(y1f + 1, Hh); m.px1 = min(x1f + 1, Ww);
        float hh = (float)max(y1f - y0f + 1, 1);
        float ww = (float)max(x1f - x0f + 1, 1);
        m.sysc = 28.0f / hh; m.sxsc = 28.0f / ww;
        m.fy0 = (float)y0f;  m.fx0 = (float)x0f;
        int c = cls[gi];
        c = max(0, min(c, NTH-1));
        m.semc = NSTUFF + c;
        m.mskoff = (gi * NTH + c) * (ROIW * ROIW);
        sb[t] = m;
        bool ov = (m.iy0 < ty0+TLY) && (m.iy1 > ty0) && (m.ix0 < tx0+TLX) && (m.ix1 > tx0);
        unsigned msk = __ballot_sync(0xffffffffu, ov);
        if (t == 0) s_tm = msk;
    }
    for (int i = t; i < NBOX*NCLS; i += 128) scnt[i] = 0;
    if (t < NSTUFF) sfl[t] = 0;
    __syncthreads();
    const unsigned tm = s_tm;

    const int x0  = tx0 + (t & 15) * 4;
    const int y   = ty0 + (t >> 4);
    const int pix = y * Ww + x0;
    const float4* s4 = (const float4*)sem + (size_t)b * NCLS * (HWp/4) + (pix >> 2);

    // 10-channel argmaxes for 4 pixels; cache thing channels 6..9
    float4 v = s4[0];
    float best[4] = {v.x, v.y, v.z, v.w};
    float smax[4] = {v.x, v.y, v.z, v.w};
    int   bi[4]   = {0,0,0,0};
    int   sp[4]   = {0,0,0,0};
    float th0[4], th1[4], th2[4], th3[4];
    #pragma unroll
    for (int c = 1; c < NCLS; ++c) {
        float4 u4 = s4[(size_t)c * (HWp/4)];
        float uu[4] = {u4.x, u4.y, u4.z, u4.w};
        #pragma unroll
        for (int p = 0; p < 4; ++p) {
            if (uu[p] > smax[p]) { smax[p] = uu[p]; sp[p] = c; }
            if (c < NSTUFF) {
                if (uu[p] > best[p]) { best[p] = uu[p]; bi[p] = c; }
            } else {
                if (c == 6) th0[p] = uu[p];
                if (c == 7) th1[p] = uu[p];
                if (c == 8) th2[p] = uu[p];
                if (c == 9) th3[p] = uu[p];
            }
        }
    }

    const float CNEG = (2.0f * sigm(-100.0f)) * (-200.0f);
    unsigned char outp[4];

    #pragma unroll
    for (int p = 0; p < 4; ++p) {
        const int x = x0 + p;
        // per-pixel cover bitmap over tile-culled boxes
        unsigned cov = 0, mm = tm;
        while (mm) {
            int n = __ffs(mm) - 1; mm &= mm - 1;
            const BoxMeta& m = sb[n];
            if (y >= m.iy0 && y < m.iy1 && x >= m.ix0 && x < m.ix1) cov |= (1u << n);
        }
        unsigned notc = ~cov;
        int ncneg = notc ? (__ffs(notc) - 1) : 32;   // first NON-covered box index
        bool applied = false;
        float bst = best[p]; int bb = bi[p];
        mm = cov;
        while (mm) {
            int n = __ffs(mm) - 1; mm &= mm - 1;
            if (!applied && ncneg < n) {               // CNEG candidate sits before box n
                if (CNEG > bst) { bst = CNEG; bb = NSTUFF + ncneg; }
                applied = true;
            }
            const BoxMeta& m = sb[n];
            int ci = m.semc - NSTUFF;
            float pi = (ci == 0) ? th0[p] : (ci == 1) ? th1[p] : (ci == 2) ? th2[p] : th3[p];
            float pm;
            if (y >= m.py0 && y < m.py1 && x >= m.px0 && x < m.px1) {
                float sy = ((float)y - m.fy0 + 0.5f) * m.sysc - 0.5f;
                sy = fminf(fmaxf(sy, 0.0f), 27.0f);
                float sx = ((float)x - m.fx0 + 0.5f) * m.sxsc - 0.5f;
                sx = fminf(fmaxf(sx, 0.0f), 27.0f);
                int yl = (int)sy, xl = (int)sx;
                int yh = min(yl + 1, 27), xh = min(xl + 1, 27);
                float wy = sy - (float)yl, wx = sx - (float)xl;
                const float* mk = roi + m.mskoff;
                float a  = mk[yl*ROIW + xl], bq = mk[yl*ROIW + xh];
                float cq = mk[yh*ROIW + xl], dq = mk[yh*ROIW + xh];
                float r0 = a  * (1.0f - wy) + cq * wy;
                float r1 = bq * (1.0f - wy) + dq * wy;
                pm = r0 * (1.0f - wx) + r1 * wx;
            } else {
                pm = -100.0f;
            }
            float val = (sigm(pi) + sigm(pm)) * (pi + pm);
            if (val > bst) { bst = val; bb = NSTUFF + n; }
        }
        if (!applied && ncneg < 32) {
            if (CNEG > bst) { bst = CNEG; bb = NSTUFF + ncneg; }
        }
        outp[p] = (unsigned char)bb;
        if (bb >= NSTUFF) atomicAdd(&scnt[(bb - NSTUFF)*NCLS + sp[p]], 1);
        else              sfl[bb] = 1;
    }

    *(uchar4*)(g_pp + (size_t)b*HWp + pix) = make_uchar4(outp[0], outp[1], outp[2], outp[3]);
    __syncthreads();

    for (int i = t; i < NBOX*NCLS; i += 128) {
        int vv = scnt[i];
        if (vv) atomicAdd(&g_counts[b][i], vv);
    }
    if (t < NSTUFF && sfl[t]) g_sflag[b][t] = 1;
}

// ---------------- pass B: label logic + counter reset (for next graph replay) ----------------
__global__ void k_passB(const int* __restrict__ cls, float* __restrict__ out) {
    int t = threadIdx.x;
    if (t < Bn) {
        int b = t;
        int  idxv[NBOX], semval[NBOX];
        bool present[NBOX], tostuff[NBOX];
        int run = 0;
        for (int n = 0; n < NBOX; ++n) {
            int s = 0, mmx = 0, mj = 0;
            for (int c = 0; c < NCLS; ++c) {
                int v = g_counts[b][n*NCLS + c];
                s += v;
                if (v > mmx) { mmx = v; mj = c; }
            }
            bool pr = s > 0;
            present[n] = pr;
            if (pr) run++;
            idxv[n] = run - 1;
            int thing = cls[b*NBOX + n] + NSTUFF;
            bool ts = (mj != thing) && (2*mmx >= max(s, 1)) && (mj < NSTUFF);
            tostuff[n] = ts;
            semval[n]  = ts ? mj : thing;
        }

        bool sp_[NSTUFF];
        for (int s = 0; s < NSTUFF; ++s) sp_[s] = (g_sflag[b][s] != 0);
        for (int n = 0; n < NBOX; ++n)
            if (present[n] && tostuff[n]) sp_[semval[n]] = true;

        int s_rank[NSTUFF]; int r = 0;
        for (int s = 0; s < NSTUFF; ++s) { if (sp_[s]) r++; s_rank[s] = r - 1; }
        int nstuff = r;

        bool ip[NBOX];
        for (int i = 0; i < NBOX; ++i) ip[i] = false;
        for (int n = 0; n < NBOX; ++n)
            if (present[n] && !tostuff[n]) ip[idxv[n]] = true;
        int i_rank[NBOX]; int r2 = 0;
        for (int i = 0; i < NBOX; ++i) { if (ip[i]) r2++; i_rank[i] = r2 - 1; }

        for (int c = 0; c < NSTUFF; ++c) g_lut[b][c] = (float)(1 + s_rank[c]);
        for (int n = 0; n < NBOX; ++n) {
            int v = 0;
            if (present[n])
                v = tostuff[n] ? (1 + s_rank[semval[n]])
                               : (1 + nstuff + i_rank[idxv[n]]);
            g_lut[b][NSTUFF + n] = (float)v;
        }

        int co[Lout];
        for (int i = 0; i < Lout; ++i) co[i] = 255;
        for (int s = 0; s < NSTUFF; ++s)
            if (sp_[s]) co[1 + s_rank[s]] = s;
        for (int n = 0; n < NBOX; ++n)
            if (present[n] && !tostuff[n]) co[1 + nstuff + i_rank[idxv[n]]] = semval[n];

        float* cbase = out + Bn*HWp + b*Lout;
        for (int i = 0; i < Lout; ++i) cbase[i] = (float)co[i];
        float* ibase = out + Bn*HWp + Bn*Lout + b*Lout;
        for (int i = 0; i < Lout; ++i) ibase[i] = 0.0f;
    }
    __syncthreads();
    // reset accumulators so the next graph replay starts from zero (deterministic)
    for (int i = t; i < Bn*NBOX*NCLS; i += blockDim.x) ((int*)g_counts)[i] = 0;
    if (t < Bn*NSTUFF) ((int*)g_sflag)[t] = 0;
}

// ---------------- pass C: seam remap (2 independent quads/thread, one per batch) ----------------
__global__ void __launch_bounds__(256) k_passC(float* __restrict__ out) {
    const int half = HWp / 4;                 // quads per batch
    int i = blockIdx.x * 256 + threadIdx.x;   // 0 .. half-1
    uchar4 p0 = ((const uchar4*)g_pp)[i];
    uchar4 p1 = ((const uchar4*)g_pp)[i + half];
    const float* l0 = g_lut[0];
    const float* l1 = g_lut[1];
    float4 o0, o1;
    o0.x = __ldg(&l0[p0.x]); o0.y = __ldg(&l0[p0.y]);
    o0.z = __ldg(&l0[p0.z]); o0.w = __ldg(&l0[p0.w]);
    o1.x = __ldg(&l1[p1.x]); o1.y = __ldg(&l1[p1.y]);
    o1.z = __ldg(&l1[p1.z]); o1.w = __ldg(&l1[p1.w]);
    ((float4*)out)[i]        = o0;
    ((float4*)out)[i + half] = o1;
}

extern "C" void kernel_launch(void* const* d_in, const int* in_sizes, int n_in,
                              void* d_out, int out_size) {
    const float* sem = nullptr;   // 10813440
    const float* roi = nullptr;   // 200704
    const float* bbx = nullptr;   // 256
    const int*   cls = nullptr;   // 64
    for (int i = 0; i < n_in; ++i) {
        switch (in_sizes[i]) {
            case 10813440: sem = (const float*)d_in[i]; break;
            case 200704:   roi = (const float*)d_in[i]; break;
            case 256:      bbx = (const float*)d_in[i]; break;
            case 64:       cls = (const int*)d_in[i];   break;
            default: break;
        }
    }
    float* out = (float*)d_out;

    k_passA<<<dim3(Ww/TLX, Hh/TLY, Bn), 128>>>(sem, roi, bbx, cls);
    k_passB<<<1, 64>>>(cls, out);
    k_passC<<<(HWp/4)/256, 256>>>(out);
}